// round 1
// baseline (speedup 1.0000x reference)
#include <cuda_runtime.h>
#include <cuda_bf16.h>

// Problem constants: B=2, H=1, LQ=LK=512, D=64, HID=128
#define NB   2
#define LQ   512
#define LK   512
#define DD   64
#define HID  128
#define RTOT 1024   // B*LQ rows

// ---------------- scratch (device globals; no allocation allowed) ------------
__device__ float g_qp[RTOT * DD];
__device__ float g_kp[RTOT * DD];
__device__ float g_vp[RTOT * DD];
__device__ float g_qa[RTOT * HID];  // qp @ W1q
__device__ float g_qb[RTOT * HID];  // qp @ W1k
__device__ float g_ka[RTOT * HID];  // kp @ W1q + b1
__device__ float g_kb[RTOT * HID];  // kp @ W1k + b1
__device__ float g_vpd[RTOT * DD];  // vp @ Wd

// ---------------- generic tiny GEMM: C[32 rows x N] = A[rows,64] @ W + bias --
template <int N>
__device__ __forceinline__ void gemm_tile(const float* __restrict__ A,
                                          const float* __restrict__ W, int ldw,
                                          const float* __restrict__ bias,
                                          float* __restrict__ C) {
    __shared__ float sA[32][64];
    __shared__ float sW[64][N];
    const int tid = threadIdx.x;           // 256 threads
    const int rowBase = blockIdx.x * 32;

    // load A tile: 32x64 floats = 512 float4
    for (int t = tid; t < 512; t += 256) {
        int r = t >> 4, g = (t & 15) << 2;
        float4 v = *(const float4*)(A + (rowBase + r) * 64 + g);
        *(float4*)&sA[r][g] = v;
    }
    // load W: 64 x N
    for (int t = tid; t < 64 * (N / 4); t += 256) {
        int r = t / (N / 4), g = (t % (N / 4)) << 2;
        float4 v = *(const float4*)(W + r * ldw + g);
        *(float4*)&sW[r][g] = v;
    }
    __syncthreads();

    const int ty = tid >> 4, tx = tid & 15;    // 16x16 threads
    constexpr int CT = N / 16;                 // cols per thread (4 or 8)
    float acc0[CT], acc1[CT];
#pragma unroll
    for (int c = 0; c < CT; ++c) { acc0[c] = 0.f; acc1[c] = 0.f; }

#pragma unroll 8
    for (int k = 0; k < 64; ++k) {
        float a0 = sA[ty * 2][k];
        float a1 = sA[ty * 2 + 1][k];
#pragma unroll
        for (int c = 0; c < CT; ++c) {
            float w = sW[k][tx * CT + c];
            acc0[c] = fmaf(a0, w, acc0[c]);
            acc1[c] = fmaf(a1, w, acc1[c]);
        }
    }
    const int r0 = rowBase + ty * 2;
#pragma unroll
    for (int c = 0; c < CT; ++c) {
        float bv = bias ? bias[tx * CT + c] : 0.f;
        C[(size_t)r0 * N + tx * CT + c]       = acc0[c] + bv;
        C[(size_t)(r0 + 1) * N + tx * CT + c] = acc1[c] + bv;
    }
}

// qp/kp/vp = {q,k,v} @ Ww + wb
__global__ __launch_bounds__(256) void proj3_kernel(const float* __restrict__ q,
                                                    const float* __restrict__ k,
                                                    const float* __restrict__ v,
                                                    const float* __restrict__ Ww,
                                                    const float* __restrict__ wb) {
    const float* A = (blockIdx.y == 0) ? q : (blockIdx.y == 1) ? k : v;
    float* C = (blockIdx.y == 0) ? g_qp : (blockIdx.y == 1) ? g_kp : g_vp;
    gemm_tile<64>(A, Ww, 64, wb, C);
}

// qa=qp@W1q, qb=qp@W1k, ka=kp@W1q+b1, kb=kp@W1k+b1
__global__ __launch_bounds__(256) void expand4_kernel(const float* __restrict__ W1,
                                                      const float* __restrict__ b1) {
    const int z = blockIdx.y;
    const float* A = (z < 2) ? g_qp : g_kp;
    const float* W = W1 + ((z == 0 || z == 2) ? 0 : 64 * HID);
    const float* bias = (z >= 2) ? b1 : nullptr;
    float* C = (z == 0) ? g_qa : (z == 1) ? g_qb : (z == 2) ? g_ka : g_kb;
    gemm_tile<HID>(A, W, HID, bias, C);
}

// vpd = vp @ Wd   (db folded into final output kernel)
__global__ __launch_bounds__(256) void vpd_kernel(const float* __restrict__ Wd) {
    gemm_tile<64>(g_vp, Wd, 64, nullptr, g_vpd);
}

// ---------------- main pairwise score kernel --------------------------------
// logits[b,i,j] = sum_h relu(qa+kb)*W2 + sum_h relu(qb+ka)*W2 + 2*b2 + mask*-1e9
__global__ __launch_bounds__(256) void scores_kernel(const float* __restrict__ W2,
                                                     const float* __restrict__ b2,
                                                     const float* __restrict__ mask,
                                                     float* __restrict__ logits) {
    __shared__ float sqa[64][33];
    __shared__ float sqb[64][33];
    __shared__ float ska[64][33];
    __shared__ float skb[64][33];
    __shared__ float sw2[32];

    const int bz = blockIdx.z;
    const int it = blockIdx.y;
    const int jt = blockIdx.x;
    const int tid = threadIdx.x;
    const int ty = tid >> 4, tx = tid & 15;

    const float* qaB = g_qa + (size_t)(bz * LQ + it * 64) * HID;
    const float* qbB = g_qb + (size_t)(bz * LQ + it * 64) * HID;
    const float* kaB = g_ka + (size_t)(bz * LK + jt * 64) * HID;
    const float* kbB = g_kb + (size_t)(bz * LK + jt * 64) * HID;

    float acc[4][4];
#pragma unroll
    for (int r = 0; r < 4; ++r)
#pragma unroll
        for (int c = 0; c < 4; ++c) acc[r][c] = 0.f;

    for (int hc = 0; hc < HID / 32; ++hc) {
        __syncthreads();  // protect previous chunk's reads
        // load 4 tiles of 64x32 (transpose-free, stride-33 padded rows)
        for (int t = tid; t < 512; t += 256) {
            int r = t >> 3, g = (t & 7) << 2;
            int off = r * HID + hc * 32 + g;
            float4 v;
            v = *(const float4*)(qaB + off);
            sqa[r][g] = v.x; sqa[r][g + 1] = v.y; sqa[r][g + 2] = v.z; sqa[r][g + 3] = v.w;
            v = *(const float4*)(qbB + off);
            sqb[r][g] = v.x; sqb[r][g + 1] = v.y; sqb[r][g + 2] = v.z; sqb[r][g + 3] = v.w;
            v = *(const float4*)(kaB + off);
            ska[r][g] = v.x; ska[r][g + 1] = v.y; ska[r][g + 2] = v.z; ska[r][g + 3] = v.w;
            v = *(const float4*)(kbB + off);
            skb[r][g] = v.x; skb[r][g + 1] = v.y; skb[r][g + 2] = v.z; skb[r][g + 3] = v.w;
        }
        if (tid < 32) sw2[tid] = W2[hc * 32 + tid];
        __syncthreads();

#pragma unroll 4
        for (int hh = 0; hh < 32; ++hh) {
            float w2v = sw2[hh];
            float a1[4], a2[4], k1[4], k2[4];
#pragma unroll
            for (int u = 0; u < 4; ++u) {
                a1[u] = sqa[ty * 4 + u][hh];
                a2[u] = sqb[ty * 4 + u][hh];
                k1[u] = ska[tx * 4 + u][hh];
                k2[u] = skb[tx * 4 + u][hh];
            }
#pragma unroll
            for (int r = 0; r < 4; ++r)
#pragma unroll
                for (int c = 0; c < 4; ++c) {
                    acc[r][c] = fmaf(fmaxf(a1[r] + k2[c], 0.f), w2v, acc[r][c]);
                    acc[r][c] = fmaf(fmaxf(a2[r] + k1[c], 0.f), w2v, acc[r][c]);
                }
        }
    }

    const float b2v = 2.0f * b2[0];
#pragma unroll
    for (int r = 0; r < 4; ++r) {
        int gi = it * 64 + ty * 4 + r;
        size_t idx = (size_t)(bz * LQ + gi) * LK + jt * 64 + tx * 4;
        float4 m = *(const float4*)(mask + idx);
        float4 o;
        o.x = acc[r][0] + b2v + m.x * -1e9f;
        o.y = acc[r][1] + b2v + m.y * -1e9f;
        o.z = acc[r][2] + b2v + m.z * -1e9f;
        o.w = acc[r][3] + b2v + m.w * -1e9f;
        *(float4*)(logits + idx) = o;
    }
}

// ---------------- softmax over j (row length 512), in place ------------------
__global__ __launch_bounds__(128) void softmax_kernel(float* __restrict__ p) {
    const int row = blockIdx.x;
    const int tid = threadIdx.x;  // 128 threads, 4 elems each
    float* base = p + (size_t)row * LK;
    float4 v = ((float4*)base)[tid];

    float m = fmaxf(fmaxf(v.x, v.y), fmaxf(v.z, v.w));
#pragma unroll
    for (int o = 16; o > 0; o >>= 1) m = fmaxf(m, __shfl_xor_sync(0xffffffffu, m, o));
    __shared__ float sm[4];
    if ((tid & 31) == 0) sm[tid >> 5] = m;
    __syncthreads();
    m = fmaxf(fmaxf(sm[0], sm[1]), fmaxf(sm[2], sm[3]));

    float e0 = __expf(v.x - m), e1 = __expf(v.y - m);
    float e2 = __expf(v.z - m), e3 = __expf(v.w - m);
    float s = (e0 + e1) + (e2 + e3);
#pragma unroll
    for (int o = 16; o > 0; o >>= 1) s += __shfl_xor_sync(0xffffffffu, s, o);
    __shared__ float ss[4];
    if ((tid & 31) == 0) ss[tid >> 5] = s;
    __syncthreads();
    s = (ss[0] + ss[1]) + (ss[2] + ss[3]);

    float inv = 1.0f / s;
    float4 o4 = make_float4(e0 * inv, e1 * inv, e2 * inv, e3 * inv);
    ((float4*)base)[tid] = o4;
}

// ---------------- out = attn @ vpd + db -------------------------------------
__global__ __launch_bounds__(256) void out_kernel(const float* __restrict__ attn,
                                                  const float* __restrict__ db,
                                                  float* __restrict__ out) {
    __shared__ float sAt[16][64];
    __shared__ float sV[64][64];
    const int b = blockIdx.y;
    const int i0 = blockIdx.x * 16;
    const int tid = threadIdx.x;        // 256
    const int ty = tid >> 6, tx = tid & 63;

    float acc[4] = {0.f, 0.f, 0.f, 0.f};

    for (int jc = 0; jc < LK / 64; ++jc) {
        __syncthreads();
        // attn tile 16x64
        {
            int r = tid >> 4, g = (tid & 15) << 2;
            float4 v = *(const float4*)(attn + (size_t)(b * LQ + i0 + r) * LK + jc * 64 + g);
            *(float4*)&sAt[r][g] = v;
        }
        // vpd tile 64x64 (1024 float4, 4 per thread)
        for (int t = tid; t < 1024; t += 256) {
            int r = t >> 4, g = (t & 15) << 2;
            float4 v = *(const float4*)(g_vpd + (size_t)(b * LK + jc * 64 + r) * DD + g);
            *(float4*)&sV[r][g] = v;
        }
        __syncthreads();

#pragma unroll 8
        for (int jj = 0; jj < 64; ++jj) {
            float vv = sV[jj][tx];
#pragma unroll
            for (int r = 0; r < 4; ++r)
                acc[r] = fmaf(sAt[ty * 4 + r][jj], vv, acc[r]);
        }
    }
    float dbv = db[tx];
#pragma unroll
    for (int r = 0; r < 4; ++r)
        out[(size_t)(b * LQ + i0 + ty * 4 + r) * DD + tx] = acc[r] + dbv;
}

// ---------------- launch ------------------------------------------------------
extern "C" void kernel_launch(void* const* d_in, const int* in_sizes, int n_in,
                              void* d_out, int out_size) {
    (void)in_sizes; (void)n_in; (void)out_size;
    const float* q    = (const float*)d_in[0];
    const float* k    = (const float*)d_in[1];
    const float* v    = (const float*)d_in[2];
    const float* mask = (const float*)d_in[3];
    const float* Ww   = (const float*)d_in[4];
    const float* wb   = (const float*)d_in[5];
    const float* Wd   = (const float*)d_in[6];
    const float* db   = (const float*)d_in[7];
    const float* W1   = (const float*)d_in[8];
    const float* b1   = (const float*)d_in[9];
    const float* W2   = (const float*)d_in[10];
    const float* b2   = (const float*)d_in[11];

    float* out  = (float*)d_out;                   // [B,H,LQ,D] = 65536 floats
    float* attn = (float*)d_out + NB * LQ * DD;    // [B,H,LQ,LK] = 524288 floats

    proj3_kernel<<<dim3(RTOT / 32, 3), 256>>>(q, k, v, Ww, wb);
    expand4_kernel<<<dim3(RTOT / 32, 4), 256>>>(W1, b1);
    vpd_kernel<<<dim3(RTOT / 32, 1), 256>>>(Wd);
    scores_kernel<<<dim3(LK / 64, LQ / 64, NB), 256>>>(W2, b2, mask, attn);
    softmax_kernel<<<dim3(NB * LQ), 128>>>(attn);
    out_kernel<<<dim3(LQ / 16, NB), 256>>>(attn, db, out);
}

// round 10
// speedup vs baseline: 1.2279x; 1.2279x over previous
#include <cuda_runtime.h>
#include <cuda_bf16.h>

// Problem constants: B=2, H=1, LQ=LK=512, D=64, HID=128
#define NB   2
#define LQ   512
#define LK   512
#define DD   64
#define HID  128
#define RTOT 1024   // B*LQ rows

// ---------------- scratch (device globals; no allocation allowed) ------------
__device__ float g_qa[RTOT * HID];  // qp @ W1q
__device__ float g_qb[RTOT * HID];  // qp @ W1k
__device__ float g_ka[RTOT * HID];  // kp @ W1q + b1
__device__ float g_kb[RTOT * HID];  // kp @ W1k + b1
__device__ float g_vpd[RTOT * DD];  // vp @ Wd

// ---------------- packed f32x2 helpers (sm_103a FADD2/FFMA2) -----------------
__device__ __forceinline__ unsigned long long f2_add(unsigned long long a, unsigned long long b) {
    unsigned long long r;
    asm("add.rn.f32x2 %0, %1, %2;" : "=l"(r) : "l"(a), "l"(b));
    return r;
}
__device__ __forceinline__ unsigned long long f2_fma(unsigned long long a, unsigned long long b, unsigned long long c) {
    unsigned long long r;
    asm("fma.rn.f32x2 %0, %1, %2, %3;" : "=l"(r) : "l"(a), "l"(b), "l"(c));
    return r;
}
__device__ __forceinline__ unsigned long long f2_relu(unsigned long long a) {
    unsigned long long r;
    asm("{\n\t"
        ".reg .f32 lo, hi;\n\t"
        "mov.b64 {lo, hi}, %1;\n\t"
        "max.f32 lo, lo, 0f00000000;\n\t"
        "max.f32 hi, hi, 0f00000000;\n\t"
        "mov.b64 %0, {lo, hi};\n\t"
        "}" : "=l"(r) : "l"(a));
    return r;
}

// ---------------- fused projections ------------------------------------------
// type 0: q -> qp=q@Ww+wb -> qa=qp@W1q, qb=qp@W1k
// type 1: k -> kp         -> ka=kp@W1q+b1, kb=kp@W1k+b1
// type 2: v -> vp         -> vpd=vp@Wd      (db folded into final kernel)
__global__ __launch_bounds__(256) void fused_proj_kernel(
    const float* __restrict__ q, const float* __restrict__ k, const float* __restrict__ v,
    const float* __restrict__ Ww, const float* __restrict__ wb,
    const float* __restrict__ W1, const float* __restrict__ b1,
    const float* __restrict__ Wd) {
    __shared__ float sA[32][64];
    __shared__ float sP[32][64];
    __shared__ float sW[64][64];

    const int type = blockIdx.y;
    const int rowBase = blockIdx.x * 32;
    const float* A = (type == 0) ? q : (type == 1) ? k : v;
    const int tid = threadIdx.x;
    const int ty = tid >> 4, tx = tid & 15;   // 16x16; 2 rows x 4 strided cols each

    // load A tile (32x64) and Ww (64x64)
    for (int t = tid; t < 512; t += 256) {
        int r = t >> 4, g = (t & 15) << 2;
        *(float4*)&sA[r][g] = *(const float4*)(A + (size_t)(rowBase + r) * 64 + g);
    }
    for (int t = tid; t < 1024; t += 256) {
        int r = t >> 4, g = (t & 15) << 2;
        *(float4*)&sW[r][g] = *(const float4*)(Ww + r * 64 + g);
    }
    __syncthreads();

    // stage 1: P = A@Ww + wb  (rows ty*2,ty*2+1; cols tx+16c)
    {
        float acc0[4] = {0.f, 0.f, 0.f, 0.f}, acc1[4] = {0.f, 0.f, 0.f, 0.f};
#pragma unroll 8
        for (int kk = 0; kk < 64; ++kk) {
            float a0 = sA[ty * 2][kk], a1 = sA[ty * 2 + 1][kk];
#pragma unroll
            for (int c = 0; c < 4; ++c) {
                float w = sW[kk][tx + 16 * c];
                acc0[c] = fmaf(a0, w, acc0[c]);
                acc1[c] = fmaf(a1, w, acc1[c]);
            }
        }
#pragma unroll
        for (int c = 0; c < 4; ++c) {
            float bv = wb[tx + 16 * c];
            sP[ty * 2][tx + 16 * c]     = acc0[c] + bv;
            sP[ty * 2 + 1][tx + 16 * c] = acc1[c] + bv;
        }
    }
    __syncthreads();  // sP ready; sW free for reuse

    if (type < 2) {
        for (int h = 0; h < 2; ++h) {
            float* dst = (h == 0) ? ((type == 0) ? g_qa : g_ka)
                                  : ((type == 0) ? g_qb : g_kb);
            const float* Wsrc = W1 + (size_t)h * 64 * HID;   // W1q rows 0..63, W1k rows 64..127
            for (int cs = 0; cs < 2; ++cs) {
                for (int t = tid; t < 1024; t += 256) {
                    int r = t >> 4, g = (t & 15) << 2;
                    *(float4*)&sW[r][g] = *(const float4*)(Wsrc + (size_t)r * HID + cs * 64 + g);
                }
                __syncthreads();
                float acc0[4] = {0.f, 0.f, 0.f, 0.f}, acc1[4] = {0.f, 0.f, 0.f, 0.f};
#pragma unroll 8
                for (int kk = 0; kk < 64; ++kk) {
                    float a0 = sP[ty * 2][kk], a1 = sP[ty * 2 + 1][kk];
#pragma unroll
                    for (int c = 0; c < 4; ++c) {
                        float w = sW[kk][tx + 16 * c];
                        acc0[c] = fmaf(a0, w, acc0[c]);
                        acc1[c] = fmaf(a1, w, acc1[c]);
                    }
                }
#pragma unroll
                for (int c = 0; c < 4; ++c) {
                    int col = cs * 64 + tx + 16 * c;
                    float bv = (type == 1) ? b1[col] : 0.f;
                    dst[(size_t)(rowBase + ty * 2) * HID + col]     = acc0[c] + bv;
                    dst[(size_t)(rowBase + ty * 2 + 1) * HID + col] = acc1[c] + bv;
                }
                __syncthreads();  // before next sW overwrite
            }
        }
    } else {
        for (int t = tid; t < 1024; t += 256) {
            int r = t >> 4, g = (t & 15) << 2;
            *(float4*)&sW[r][g] = *(const float4*)(Wd + r * 64 + g);
        }
        __syncthreads();
        float acc0[4] = {0.f, 0.f, 0.f, 0.f}, acc1[4] = {0.f, 0.f, 0.f, 0.f};
#pragma unroll 8
        for (int kk = 0; kk < 64; ++kk) {
            float a0 = sP[ty * 2][kk], a1 = sP[ty * 2 + 1][kk];
#pragma unroll
            for (int c = 0; c < 4; ++c) {
                float w = sW[kk][tx + 16 * c];
                acc0[c] = fmaf(a0, w, acc0[c]);
                acc1[c] = fmaf(a1, w, acc1[c]);
            }
        }
#pragma unroll
        for (int c = 0; c < 4; ++c) {
            int col = tx + 16 * c;
            g_vpd[(size_t)(rowBase + ty * 2) * DD + col]     = acc0[c];
            g_vpd[(size_t)(rowBase + ty * 2 + 1) * DD + col] = acc1[c];
        }
    }
}

// ---------------- pairwise score kernel (packed f32x2) -----------------------
// Tile: 64 i-rows x 32 j-cols. Grid (LK/32, LQ/64, NB) = 256 blocks, 2/SM.
// logits[b,i,j] = sum_h relu(qa+kb)*W2 + sum_h relu(qb+ka)*W2 + 2*b2 + mask*-1e9
__global__ __launch_bounds__(256, 2) void scores_kernel(
    const float* __restrict__ W2, const float* __restrict__ b2,
    const float* __restrict__ mask, float* __restrict__ logits) {
    __shared__ float2 sqa[64][33];   // (a,a) duplicated for packed broadcast
    __shared__ float2 sqb[64][33];
    __shared__ float2 ska[16][33];   // (ka[2c],ka[2c+1]) packed over adjacent j
    __shared__ float2 skb[16][33];
    __shared__ float2 sw2[32];       // (w2,w2)

    const int bz = blockIdx.z, it = blockIdx.y, jt = blockIdx.x;
    const int tid = threadIdx.x;
    const int ty = tid >> 4, tx = tid & 15;   // rows ty*4..+3, col pair tx

    const float* qaB = g_qa + (size_t)(bz * LQ + it * 64) * HID;
    const float* qbB = g_qb + (size_t)(bz * LQ + it * 64) * HID;
    const float* kaB = g_ka + (size_t)(bz * LK + jt * 32) * HID;
    const float* kbB = g_kb + (size_t)(bz * LK + jt * 32) * HID;

    unsigned long long acc[4] = {0ull, 0ull, 0ull, 0ull};

    for (int hc = 0; hc < HID / 32; ++hc) {
        __syncthreads();   // protect previous chunk's reads
        // a-side tiles: 64 rows x 32 hh, duplicated into float2
        for (int t = tid; t < 512; t += 256) {
            int r = t >> 3, g = (t & 7) << 2;
            float4 va = *(const float4*)(qaB + (size_t)r * HID + hc * 32 + g);
            sqa[r][g]     = make_float2(va.x, va.x);
            sqa[r][g + 1] = make_float2(va.y, va.y);
            sqa[r][g + 2] = make_float2(va.z, va.z);
            sqa[r][g + 3] = make_float2(va.w, va.w);
            float4 vb = *(const float4*)(qbB + (size_t)r * HID + hc * 32 + g);
            sqb[r][g]     = make_float2(vb.x, vb.x);
            sqb[r][g + 1] = make_float2(vb.y, vb.y);
            sqb[r][g + 2] = make_float2(vb.z, vb.z);
            sqb[r][g + 3] = make_float2(vb.w, vb.w);
        }
        // k-side tiles: 32 rows x 32 hh, packed pairs of adjacent j rows
        {
            int j = tid >> 3, g = (tid & 7) << 2;     // 256 threads cover 32x8 float4
            int c2 = j >> 1, half = j & 1;
            float* sa = (float*)ska;
            float* sb = (float*)skb;
            float4 va = *(const float4*)(kaB + (size_t)j * HID + hc * 32 + g);
            sa[(c2 * 33 + g) * 2 + half]     = va.x;
            sa[(c2 * 33 + g + 1) * 2 + half] = va.y;
            sa[(c2 * 33 + g + 2) * 2 + half] = va.z;
            sa[(c2 * 33 + g + 3) * 2 + half] = va.w;
            float4 vb = *(const float4*)(kbB + (size_t)j * HID + hc * 32 + g);
            sb[(c2 * 33 + g) * 2 + half]     = vb.x;
            sb[(c2 * 33 + g + 1) * 2 + half] = vb.y;
            sb[(c2 * 33 + g + 2) * 2 + half] = vb.z;
            sb[(c2 * 33 + g + 3) * 2 + half] = vb.w;
        }
        if (tid < 32) {
            float w = W2[hc * 32 + tid];
            sw2[tid] = make_float2(w, w);
        }
        __syncthreads();

#pragma unroll 8
        for (int hh = 0; hh < 32; ++hh) {
            unsigned long long w2v = *(const unsigned long long*)&sw2[hh];
            unsigned long long k1  = *(const unsigned long long*)&ska[tx][hh];
            unsigned long long k2  = *(const unsigned long long*)&skb[tx][hh];
#pragma unroll
            for (int r = 0; r < 4; ++r) {
                unsigned long long a1 = *(const unsigned long long*)&sqa[ty * 4 + r][hh];
                unsigned long long a2 = *(const unsigned long long*)&sqb[ty * 4 + r][hh];
                acc[r] = f2_fma(f2_relu(f2_add(a1, k2)), w2v, acc[r]);
                acc[r] = f2_fma(f2_relu(f2_add(a2, k1)), w2v, acc[r]);
            }
        }
    }

    const float b2v = 2.0f * b2[0];
#pragma unroll
    for (int r = 0; r < 4; ++r) {
        float2 a = *(float2*)&acc[r];
        int gi = it * 64 + ty * 4 + r;
        size_t idx = (size_t)(bz * LQ + gi) * LK + jt * 32 + tx * 2;
        float2 m = *(const float2*)(mask + idx);
        float2 o;
        o.x = a.x + b2v + m.x * -1e9f;
        o.y = a.y + b2v + m.y * -1e9f;
        *(float2*)(logits + idx) = o;
    }
}

// ---------------- fused softmax + output GEMM --------------------------------
// Block: 8 i-rows. Softmax each row (warp per row), write normalized attn to
// gmem + smem, then out[8x64] = attn[8x512] @ vpd[512x64] + db.
__global__ __launch_bounds__(256) void softout_kernel(
    float* __restrict__ attn, const float* __restrict__ db, float* __restrict__ out) {
    __shared__ float sAttn[8][512];
    __shared__ float sV[64][64];

    const int b = blockIdx.y;
    const int i0 = blockIdx.x * 8;
    const int tid = threadIdx.x;
    const int w = tid >> 5, l = tid & 31;   // warp w handles row i0+w

    // ---- softmax over row (512 elems, 16 per lane as 4 float4) ----
    float* rowp = attn + (size_t)(b * LQ + i0 + w) * LK;
    float4 vv[4];
    float m = -1e30f;
#pragma unroll
    for (int kk = 0; kk < 4; ++kk) {
        vv[kk] = ((const float4*)rowp)[l + 32 * kk];
        m = fmaxf(m, fmaxf(fmaxf(vv[kk].x, vv[kk].y), fmaxf(vv[kk].z, vv[kk].w)));
    }
#pragma unroll
    for (int o = 16; o > 0; o >>= 1) m = fmaxf(m, __shfl_xor_sync(0xffffffffu, m, o));
    float s = 0.f;
#pragma unroll
    for (int kk = 0; kk < 4; ++kk) {
        vv[kk].x = __expf(vv[kk].x - m);
        vv[kk].y = __expf(vv[kk].y - m);
        vv[kk].z = __expf(vv[kk].z - m);
        vv[kk].w = __expf(vv[kk].w - m);
        s += (vv[kk].x + vv[kk].y) + (vv[kk].z + vv[kk].w);
    }
#pragma unroll
    for (int o = 16; o > 0; o >>= 1) s += __shfl_xor_sync(0xffffffffu, s, o);
    float inv = 1.0f / s;
#pragma unroll
    for (int kk = 0; kk < 4; ++kk) {
        float4 o4 = make_float4(vv[kk].x * inv, vv[kk].y * inv, vv[kk].z * inv, vv[kk].w * inv);
        ((float4*)rowp)[l + 32 * kk] = o4;                 // normalized attn (output #2)
        *(float4*)&sAttn[w][(l + 32 * kk) * 4] = o4;
    }

    // ---- out = sAttn @ vpd + db : thread handles row w, cols 2l,2l+1 ----
    float acc0 = 0.f, acc1 = 0.f;
    for (int jc = 0; jc < LK / 64; ++jc) {
        __syncthreads();
        for (int t = tid; t < 1024; t += 256) {
            int r = t >> 4, g = (t & 15) << 2;
            *(float4*)&sV[r][g] = *(const float4*)(g_vpd + (size_t)(b * LK + jc * 64 + r) * DD + g);
        }
        __syncthreads();
#pragma unroll 8
        for (int jj = 0; jj < 64; ++jj) {
            float a = sAttn[w][jc * 64 + jj];
            float2 v2 = *(const float2*)&sV[jj][l * 2];
            acc0 = fmaf(a, v2.x, acc0);
            acc1 = fmaf(a, v2.y, acc1);
        }
    }
    int col = l * 2;
    size_t oidx = (size_t)(b * LQ + i0 + w) * DD + col;
    out[oidx]     = acc0 + db[col];
    out[oidx + 1] = acc1 + db[col + 1];
}

// ---------------- launch ------------------------------------------------------
extern "C" void kernel_launch(void* const* d_in, const int* in_sizes, int n_in,
                              void* d_out, int out_size) {
    (void)in_sizes; (void)n_in; (void)out_size;
    const float* q    = (const float*)d_in[0];
    const float* k    = (const float*)d_in[1];
    const float* v    = (const float*)d_in[2];
    const float* mask = (const float*)d_in[3];
    const float* Ww   = (const float*)d_in[4];
    const float* wb   = (const float*)d_in[5];
    const float* Wd   = (const float*)d_in[6];
    const float* db   = (const float*)d_in[7];
    const float* W1   = (const float*)d_in[8];
    const float* b1   = (const float*)d_in[9];
    const float* W2   = (const float*)d_in[10];
    const float* b2   = (const float*)d_in[11];

    float* out  = (float*)d_out;                   // [B,H,LQ,D] = 65536 floats
    float* attn = (float*)d_out + NB * LQ * DD;    // [B,H,LQ,LK] = 524288 floats

    fused_proj_kernel<<<dim3(RTOT / 32, 3), 256>>>(q, k, v, Ww, wb, W1, b1, Wd);
    scores_kernel<<<dim3(LK / 32, LQ / 64, NB), 256>>>(W2, b2, mask, attn);
    softout_kernel<<<dim3(LQ / 8, NB), 256>>>(attn, db, out);
}